// round 5
// baseline (speedup 1.0000x reference)
#include <cuda_runtime.h>
#include <math.h>

#define NB 64
#define NS 512
#define ND 1024
#define NH 1024
#define NK 4
#define DTC 0.05f

#define NCTA 128      // persistent CTAs (must all be co-resident)
#define GJ   32       // j-groups
#define BPC  16       // batches per CTA (64 / (NCTA/GJ))
#define JPC  32       // h-columns per CTA

// -------- device scratch (static allocation only; no cudaMalloc allowed) ----
__device__ float g_U[(size_t)NB * NS * NH];     // input projection, 128 MB
__device__ float g_hT[2 * NH * NB];             // double-buffered transposed h
__device__ float g_alpha[NB];
__device__ unsigned int g_count = 0;
__device__ unsigned int g_gen = 0;

// ---------------------------------------------------------------------------
// alpha[b] = exp(-dt / sum_k tau_k * softmax(complexity[b]*mw[k] + mb[k]))
// ---------------------------------------------------------------------------
__global__ void alpha_kernel(const float* __restrict__ comp,
                             const float* __restrict__ mw,
                             const float* __restrict__ mb,
                             const float* __restrict__ tau) {
    int b = threadIdx.x;
    if (b >= NB) return;
    float c = comp[b];
    float lg[NK];
    float mx = -1e30f;
#pragma unroll
    for (int k = 0; k < NK; k++) { lg[k] = c * mw[k] + mb[k]; mx = fmaxf(mx, lg[k]); }
    float se = 0.f;
#pragma unroll
    for (int k = 0; k < NK; k++) { lg[k] = expf(lg[k] - mx); se += lg[k]; }
    float mt = 0.f;
#pragma unroll
    for (int k = 0; k < NK; k++) mt += tau[k] * lg[k];
    mt /= se;
    g_alpha[b] = expf(-DTC / mt);
}

__global__ void zero_hT() {
    int i = blockIdx.x * blockDim.x + threadIdx.x;
    if (i < 2 * NH * NB) g_hT[i] = 0.f;
}

// ---------------------------------------------------------------------------
// U[m][n] = sum_k x[m][k] * W_in[n][k] + bias[n]
// M = B*S = 32768, N = H = 1024, K = D = 1024. 128x128 tile, Kt=8, 8x8/thread.
// ---------------------------------------------------------------------------
__global__ __launch_bounds__(256) void gemm_u(const float* __restrict__ A,
                                              const float* __restrict__ W,
                                              const float* __restrict__ bias) {
    __shared__ float As[8][128];
    __shared__ float Bs[8][128];
    int tid = threadIdx.x;
    int m0 = blockIdx.y * 128;
    int n0 = blockIdx.x * 128;

    int lr = tid >> 1;            // 0..127 (tile row)
    int lk = (tid & 1) * 4;       // 0 or 4
    const float* Ag = A + (size_t)(m0 + lr) * ND + lk;
    const float* Bg = W + (size_t)(n0 + lr) * ND + lk;

    int tx = tid & 15;            // n direction (8 cols each)
    int ty = tid >> 4;            // m direction (8 rows each)

    float acc[8][8];
#pragma unroll
    for (int i = 0; i < 8; i++)
#pragma unroll
        for (int j = 0; j < 8; j++) acc[i][j] = 0.f;

    for (int kt = 0; kt < ND; kt += 8) {
        float4 av = *(const float4*)(Ag + kt);
        float4 bv = *(const float4*)(Bg + kt);
        __syncthreads();
        As[lk + 0][lr] = av.x; As[lk + 1][lr] = av.y;
        As[lk + 2][lr] = av.z; As[lk + 3][lr] = av.w;
        Bs[lk + 0][lr] = bv.x; Bs[lk + 1][lr] = bv.y;
        Bs[lk + 2][lr] = bv.z; Bs[lk + 3][lr] = bv.w;
        __syncthreads();
#pragma unroll
        for (int k = 0; k < 8; k++) {
            float a[8], b[8];
            *(float4*)&a[0] = *(const float4*)&As[k][ty * 8];
            *(float4*)&a[4] = *(const float4*)&As[k][ty * 8 + 4];
            *(float4*)&b[0] = *(const float4*)&Bs[k][tx * 8];
            *(float4*)&b[4] = *(const float4*)&Bs[k][tx * 8 + 4];
#pragma unroll
            for (int i = 0; i < 8; i++)
#pragma unroll
                for (int j = 0; j < 8; j++)
                    acc[i][j] = fmaf(a[i], b[j], acc[i][j]);
        }
    }

    float bv0[8];
#pragma unroll
    for (int j = 0; j < 8; j++) bv0[j] = bias[n0 + tx * 8 + j];
#pragma unroll
    for (int i = 0; i < 8; i++) {
        float* Cp = g_U + (size_t)(m0 + ty * 8 + i) * NH + n0 + tx * 8;
        float4 v0 = make_float4(acc[i][0] + bv0[0], acc[i][1] + bv0[1],
                                acc[i][2] + bv0[2], acc[i][3] + bv0[3]);
        float4 v1 = make_float4(acc[i][4] + bv0[4], acc[i][5] + bv0[5],
                                acc[i][6] + bv0[6], acc[i][7] + bv0[7]);
        *(float4*)(Cp)     = v0;
        *(float4*)(Cp + 4) = v1;
    }
}

// ---------------------------------------------------------------------------
// Persistent recurrent kernel. 128 CTAs (4 batch-groups x 32 j-groups),
// 128 threads. W_rec slice transposed in SMEM, h double-buffered in L2
// (transposed layout), h-state in registers. One grid barrier per step.
// ---------------------------------------------------------------------------
__device__ __forceinline__ void grid_barrier() {
    __syncthreads();
    if (threadIdx.x == 0) {
        volatile unsigned int* genp = &g_gen;
        unsigned int g = *genp;
        __threadfence();                       // release this CTA's writes
        unsigned int a = atomicAdd(&g_count, 1u);
        if (a == NCTA - 1) {
            *(volatile unsigned int*)&g_count = 0;
            __threadfence();
            atomicAdd(&g_gen, 1u);             // release all
        } else {
            while (*genp == g) __nanosleep(64);
        }
    }
    __syncthreads();
}

__global__ __launch_bounds__(128, 1) void liquid_kernel(const float* __restrict__ Wr,
                                                        float* __restrict__ out) {
    extern __shared__ float smem[];
    float* Wt = smem;                  // [1024][32]  transposed W_rec slice (128 KB)
    float* hs = smem + 1024 * 32;      // [1024][16]  staged transposed h slice (64 KB)

    int cta = blockIdx.x;
    int jg = cta & (GJ - 1);
    int bg = cta >> 5;
    int j0 = jg * JPC;
    int b0 = bg * BPC;
    int tid = threadIdx.x;
    int tb = tid & 7;                  // batch-pair index   (8  -> 16 batches)
    int tj = tid >> 3;                 // column-pair index  (16 -> 32 columns)
    int bb = 2 * tb, jj = 2 * tj;

    // ---- one-time: load W_rec rows j0..j0+31, transposed into SMEM ----
    {
        int r  = tid >> 2;             // 0..31  (j within slice)
        int kq = (tid & 3) * 4;        // 0,4,8,12
        const float* wg = Wr + (size_t)(j0 + r) * NH + kq;
#pragma unroll 4
        for (int kk = 0; kk < NH; kk += 16) {
            float4 v = *(const float4*)(wg + kk);
            Wt[(kk + kq + 0) * 32 + r] = v.x;
            Wt[(kk + kq + 1) * 32 + r] = v.y;
            Wt[(kk + kq + 2) * 32 + r] = v.z;
            Wt[(kk + kq + 3) * 32 + r] = v.w;
        }
    }

    float a0 = g_alpha[b0 + bb];
    float a1 = g_alpha[b0 + bb + 1];
    float na0 = 1.f - a0, na1 = 1.f - a1;
    float h00 = 0.f, h01 = 0.f, h10 = 0.f, h11 = 0.f;
    __syncthreads();

    int bgl0 = b0 + bb;
    int jgl  = j0 + jj;
    size_t out_stride = (size_t)NS * NH;

    int sk = tid >> 2;                 // staging: k row
    int sc = (tid & 3) * 4;            // staging: 4-float column chunk

    for (int t = 0; t < NS; t++) {
        const float* rbuf = g_hT + (size_t)(t & 1) * NH * NB;        // read h_t
        float*       wbuf = g_hT + (size_t)((t + 1) & 1) * NH * NB;  // write h_{t+1}

        // ---- stage transposed h slice [1024][16] into SMEM (L2, bypass L1) ----
        {
            const float4* src = (const float4*)(rbuf + (size_t)sk * NB + b0 + sc);
            float4*       dst = (float4*)(hs + sk * 16 + sc);
#pragma unroll 8
            for (int kk = 0; kk < NH; kk += 32) {
                dst[kk * 4] = __ldcg(src + kk * 16);
            }
        }
        __syncthreads();

        // ---- 2x2 outer-product dot over k = 0..1023 ----
        float c00 = 0.f, c01 = 0.f, c10 = 0.f, c11 = 0.f;
        const float2* wp = (const float2*)(Wt + jj);
        const float2* hp = (const float2*)(hs + bb);
#pragma unroll 8
        for (int k = 0; k < NH; k++) {
            float2 wv = wp[k * 16];    // Wt[k][jj..jj+1]
            float2 hv = hp[k * 8];     // hs[k][bb..bb+1]
            c00 = fmaf(hv.x, wv.x, c00);
            c01 = fmaf(hv.x, wv.y, c01);
            c10 = fmaf(hv.y, wv.x, c10);
            c11 = fmaf(hv.y, wv.y, c11);
        }

        // ---- add u_t, activation, state update ----
        size_t ro0 = ((size_t)bgl0 * NS + t) * NH + jgl;
        size_t ro1 = ro0 + out_stride;
        float2 u0 = *(const float2*)(g_U + ro0);
        float2 u1 = *(const float2*)(g_U + ro1);
        h00 = a0 * h00 + na0 * tanhf(c00 + u0.x);
        h01 = a0 * h01 + na0 * tanhf(c01 + u0.y);
        h10 = a1 * h10 + na1 * tanhf(c10 + u1.x);
        h11 = a1 * h11 + na1 * tanhf(c11 + u1.y);

        // ---- write outputs (normal layout) + next-state (transposed, L2) ----
        *(float2*)(out + ro0) = make_float2(h00, h01);
        *(float2*)(out + ro1) = make_float2(h10, h11);
        __stcg((float2*)(wbuf + (size_t)jgl * NB + bgl0),       make_float2(h00, h10));
        __stcg((float2*)(wbuf + (size_t)(jgl + 1) * NB + bgl0), make_float2(h01, h11));

        grid_barrier();
    }

    // ---- h_final appended after output[B,S,H] ----
    float* hf = out + (size_t)NB * NS * NH;
    *(float2*)(hf + (size_t)bgl0 * NH + jgl)       = make_float2(h00, h01);
    *(float2*)(hf + (size_t)(bgl0 + 1) * NH + jgl) = make_float2(h10, h11);
}

// ---------------------------------------------------------------------------
extern "C" void kernel_launch(void* const* d_in, const int* in_sizes, int n_in,
                              void* d_out, int out_size) {
    const float* x    = (const float*)d_in[0];
    const float* comp = (const float*)d_in[1];
    const float* Wrec = (const float*)d_in[2];
    const float* Win  = (const float*)d_in[3];
    const float* bias = (const float*)d_in[4];
    const float* tau  = (const float*)d_in[5];
    const float* mw   = (const float*)d_in[6];
    const float* mb   = (const float*)d_in[7];
    float* out = (float*)d_out;

    const int smem_bytes = (1024 * 32 + 1024 * 16) * (int)sizeof(float);  // 196608
    cudaFuncSetAttribute(liquid_kernel, cudaFuncAttributeMaxDynamicSharedMemorySize,
                         smem_bytes);

    alpha_kernel<<<1, 64>>>(comp, mw, mb, tau);
    zero_hT<<<(2 * NH * NB + 1023) / 1024, 1024>>>();
    dim3 gemm_grid(NH / 128, (NB * NS) / 128);   // (8, 256)
    gemm_u<<<gemm_grid, 256>>>(x, Win, bias);
    liquid_kernel<<<NCTA, 128, smem_bytes>>>(Wrec, out);
}